// round 16
// baseline (speedup 1.0000x reference)
#include <cuda_runtime.h>
#include <cuda_bf16.h>

// CompositeValueNoise, spatially-binned v14.
// vs R14 (best 94.0us; R15's FFMA2 regressed and is reverted): main kernel
// processes 2 CONSECUTIVE SORTED points per thread. Consecutive sorted points
// share their interpolation cell at ~99/97/93/35% for V16/32/64/128, so point
// B reloads a level's 8 corners ONLY if its cell differs from A's (register
// reuse is bit-exact: same cell -> same corner values). Predicated-off lanes
// return no data, cutting main's L1 data-return traffic ~40% (R15 showed
// return bandwidth, not issue, is the wall).

#define N_FIELDS 4
#define MAXN 2000000
#define BBITS 6
#define BDIM (1 << BBITS)            // 64
#define NBUCK (BDIM * BDIM * BDIM)   // 262144
#define SCAN_BLKS (NBUCK / 1024)     // 256

__device__ int    g_hist[NBUCK];     // zero at load; re-zeroed by main kernel
__device__ int    g_counter;
__device__ float4 g_sorted[MAXN];

__device__ __forceinline__ int cell_key(float px, float py, float pz) {
    int ci = min(max((int)(px * (float)BDIM), 0), BDIM - 1);
    int cj = min(max((int)(py * (float)BDIM), 0), BDIM - 1);
    int ck = min(max((int)(pz * (float)BDIM), 0), BDIM - 1);
    return (ci << (2 * BBITS)) | (cj << BBITS) | ck;   // k innermost
}

__global__ void hist_kernel(const float* __restrict__ x, int n) {
    int t = blockIdx.x * blockDim.x + threadIdx.x;
    int p0 = t * 4;
    if (p0 >= n) return;
    if (p0 + 4 <= n) {
        const float4* xv = reinterpret_cast<const float4*>(x) + 3 * (size_t)t;
        float4 a = __ldcs(xv + 0), b = __ldcs(xv + 1), c = __ldcs(xv + 2);
        atomicAdd(&g_hist[cell_key(a.x, a.y, a.z)], 1);
        atomicAdd(&g_hist[cell_key(a.w, b.x, b.y)], 1);
        atomicAdd(&g_hist[cell_key(b.z, b.w, c.x)], 1);
        atomicAdd(&g_hist[cell_key(c.y, c.z, c.w)], 1);
    } else {
        for (int p = p0; p < n; ++p)
            atomicAdd(&g_hist[cell_key(x[3*p], x[3*p+1], x[3*p+2])], 1);
    }
}

// Coalesced block scan of 1024 ints; block takes its global segment base via
// one early atomicAdd on g_counter, folded into the stored prefixes, so
// g_hist ends holding ABSOLUTE exclusive bucket bases. Segment order is
// run-arbitrary; each point's slot and value are unchanged -> deterministic.
__global__ void scan1_kernel() {
    __shared__ int warp_sums[8];
    __shared__ int s_base;
    int b = blockIdx.x, t = threadIdx.x;
    int lane = t & 31, wid = t >> 5;
    int base = b * 1024 + t * 4;

    int4 v = *reinterpret_cast<int4*>(&g_hist[base]);
    int tot = v.x + v.y + v.z + v.w;

    int inc = tot;
    #pragma unroll
    for (int o = 1; o < 32; o <<= 1) {
        int u = __shfl_up_sync(0xffffffffu, inc, o);
        if (lane >= o) inc += u;
    }
    if (lane == 31) warp_sums[wid] = inc;
    __syncthreads();
    if (wid == 0 && lane < 8) {
        int w = warp_sums[lane];
        #pragma unroll
        for (int o = 1; o < 8; o <<= 1) {
            int u = __shfl_up_sync(0xffu, w, o);
            if (lane >= o) w += u;
        }
        warp_sums[lane] = w;
        if (lane == 7) s_base = atomicAdd(&g_counter, w);  // w == block total
    }
    __syncthreads();
    int excl = s_base + (wid ? warp_sums[wid - 1] : 0) + inc - tot;

    int4 r;
    r.x = excl;
    r.y = excl + v.x;
    r.z = excl + v.x + v.y;
    r.w = excl + v.x + v.y + v.z;
    *reinterpret_cast<int4*>(&g_hist[base]) = r;
}

__device__ __forceinline__ void scatter_one(float px, float py, float pz, int i) {
    int pos = atomicAdd(&g_hist[cell_key(px, py, pz)], 1);
    __stcg(&g_sorted[pos], make_float4(px, py, pz, __int_as_float(i)));
}

__global__ void scatter_kernel(const float* __restrict__ x, int n) {
    int t = blockIdx.x * blockDim.x + threadIdx.x;
    int p0 = t * 4;
    if (p0 >= n) return;
    if (p0 + 4 <= n) {
        const float4* xv = reinterpret_cast<const float4*>(x) + 3 * (size_t)t;
        float4 a = __ldcs(xv + 0), b = __ldcs(xv + 1), c = __ldcs(xv + 2);
        scatter_one(a.x, a.y, a.z, p0 + 0);
        scatter_one(a.w, b.x, b.y, p0 + 1);
        scatter_one(b.z, b.w, c.x, p0 + 2);
        scatter_one(c.y, c.z, c.w, p0 + 3);
    } else {
        for (int p = p0; p < n; ++p)
            scatter_one(x[3*p], x[3*p+1], x[3*p+2], p);
    }
}

__device__ __forceinline__ float4 ld4(const float* __restrict__ p) {
    return __ldg(reinterpret_cast<const float4*>(p));
}

__device__ __forceinline__ float4 lerp4(float4 a, float4 b, float w) {
    float4 r;
    r.x = fmaf(w, b.x - a.x, a.x);
    r.y = fmaf(w, b.y - a.y, a.y);
    r.z = fmaf(w, b.z - a.z, a.z);
    r.w = fmaf(w, b.w - a.w, a.w);
    return r;
}

struct Lv {
    const float* base;
    int s0, s1;
    float wx, wy, wz;
};

__device__ __forceinline__ Lv prep(const float* __restrict__ V, int res,
                                   float px, float py, float pz) {
    const float resf = (float)res;
    float xs = px * resf, ys = py * resf, zs = pz * resf;
    // x in [0,1) and xs >= 0: trunc == floor.
    int i0 = (int)xs, j0 = (int)ys, k0 = (int)zs;
    float tx = xs - (float)i0, ty = ys - (float)j0, tz = zs - (float)k0;
    Lv L;
    L.wx = (3.0f - 2.0f * tx) * tx * tx;
    L.wy = (3.0f - 2.0f * ty) * ty * ty;
    L.wz = (3.0f - 2.0f * tz) * tz * tz;
    const int r1 = res + 1;
    L.s1 = r1 * N_FIELDS;
    L.s0 = r1 * L.s1;
    L.base = V + (size_t)i0 * L.s0 + (size_t)j0 * L.s1 + (size_t)k0 * N_FIELDS;
    return L;
}

__device__ __forceinline__ void do_loads8(const Lv& L, float4 v[8]) {
    v[0] = ld4(L.base);
    v[1] = ld4(L.base + N_FIELDS);
    v[2] = ld4(L.base + L.s1);
    v[3] = ld4(L.base + L.s1 + N_FIELDS);
    v[4] = ld4(L.base + L.s0);
    v[5] = ld4(L.base + L.s0 + N_FIELDS);
    v[6] = ld4(L.base + L.s0 + L.s1);
    v[7] = ld4(L.base + L.s0 + L.s1 + N_FIELDS);
}

__device__ __forceinline__ float4 interp8(const Lv& L, const float4 v[8]) {
    // reference order: dim0 (wx), dim1 (wy), dim2 (wz)
    float4 a00 = lerp4(v[0], v[4], L.wx);
    float4 a01 = lerp4(v[1], v[5], L.wx);
    float4 a10 = lerp4(v[2], v[6], L.wx);
    float4 a11 = lerp4(v[3], v[7], L.wx);
    float4 b0 = lerp4(a00, a10, L.wy);
    float4 b1 = lerp4(a01, a11, L.wy);
    return lerp4(b0, b1, L.wz);
}

__device__ __forceinline__ float4 combine(float4 n0, float4 n1,
                                          float4 n2, float4 n3) {
    float4 acc;
    acc.x = fmaf(0.125f, n3.x, fmaf(0.25f, n2.x, fmaf(0.5f, n1.x, n0.x)));
    acc.y = fmaf(0.125f, n3.y, fmaf(0.25f, n2.y, fmaf(0.5f, n1.y, n0.y)));
    acc.z = fmaf(0.125f, n3.z, fmaf(0.25f, n2.z, fmaf(0.5f, n1.z, n0.z)));
    acc.w = fmaf(0.125f, n3.w, fmaf(0.25f, n2.w, fmaf(0.5f, n1.w, n0.w)));
    return acc;
}

__global__ void __launch_bounds__(128, 8) composite_value_noise_kernel(
    const float* __restrict__ V16,
    const float* __restrict__ V32,
    const float* __restrict__ V64,
    const float* __restrict__ V128,
    float* __restrict__ out,
    int n)
{
    int t = blockIdx.x * blockDim.x + threadIdx.x;
    int pA = 2 * t;

    if (pA < n) {
        float4 ptA = __ldcs(&g_sorted[pA]);
        bool hasB = (pA + 1) < n;
        float4 ptB = hasB ? __ldcs(&g_sorted[pA + 1]) : ptA;

        float4 va[8], vb[8];

        // ---- Point A, levels 16+32 (loads batched) ----
        Lv a0 = prep(V16, 16, ptA.x, ptA.y, ptA.z);
        Lv a1 = prep(V32, 32, ptA.x, ptA.y, ptA.z);
        do_loads8(a0, va);
        do_loads8(a1, vb);
        float4 nA0 = interp8(a0, va);
        float4 nA1 = interp8(a1, vb);

        // ---- Point B, levels 16+32: reload only if cell differs ----
        Lv b0 = prep(V16, 16, ptB.x, ptB.y, ptB.z);
        Lv b1 = prep(V32, 32, ptB.x, ptB.y, ptB.z);
        if (b0.base != a0.base) do_loads8(b0, va);
        if (b1.base != a1.base) do_loads8(b1, vb);
        float4 nB0 = interp8(b0, va);
        float4 nB1 = interp8(b1, vb);

        // ---- Point A, levels 64+128 ----
        Lv a2 = prep(V64, 64, ptA.x, ptA.y, ptA.z);
        Lv a3 = prep(V128, 128, ptA.x, ptA.y, ptA.z);
        do_loads8(a2, va);
        do_loads8(a3, vb);
        float4 nA2 = interp8(a2, va);
        float4 nA3 = interp8(a3, vb);

        // ---- Point B, levels 64+128 ----
        Lv b2 = prep(V64, 64, ptB.x, ptB.y, ptB.z);
        Lv b3 = prep(V128, 128, ptB.x, ptB.y, ptB.z);
        if (b2.base != a2.base) do_loads8(b2, va);
        if (b3.base != a3.base) do_loads8(b3, vb);
        float4 nB2 = interp8(b2, va);
        float4 nB3 = interp8(b3, vb);

        float4 accA = combine(nA0, nA1, nA2, nA3);
        __stcg(reinterpret_cast<float4*>(out) + __float_as_int(ptA.w), accA);
        if (hasB) {
            float4 accB = combine(nB0, nB1, nB2, nB3);
            __stcg(reinterpret_cast<float4*>(out) + __float_as_int(ptB.w), accB);
        }
    }

    // Tail: restore the "g_hist is zero" invariant for the next invocation
    // (main kernel never reads g_hist; half-size grid -> 2 int4 per thread).
    int z = blockIdx.x * blockDim.x + threadIdx.x;
    #pragma unroll
    for (int r = 0; r < 2; ++r) {
        int zz = z + r * ((NBUCK / 4) / 2);
        if (zz < NBUCK / 4)
            __stcg(reinterpret_cast<int4*>(g_hist) + zz, make_int4(0, 0, 0, 0));
    }
    if (z == 0) g_counter = 0;
}

extern "C" void kernel_launch(void* const* d_in, const int* in_sizes, int n_in,
                              void* d_out, int out_size) {
    const float* x    = (const float*)d_in[0];
    const float* V16  = (const float*)d_in[1];
    const float* V32  = (const float*)d_in[2];
    const float* V64  = (const float*)d_in[3];
    const float* V128 = (const float*)d_in[4];
    float* out = (float*)d_out;

    int n = in_sizes[0] / 3;
    const int T = 256;
    int nquads = (n + 3) / 4;

    hist_kernel<<<(nquads + T - 1) / T, T>>>(x, n);
    scan1_kernel<<<SCAN_BLKS, 256>>>();
    scatter_kernel<<<(nquads + T - 1) / T, T>>>(x, n);

    const int TM = 128;
    int nhalf = (n + 1) / 2;
    int blocks = (nhalf + TM - 1) / TM;
    composite_value_noise_kernel<<<blocks, TM>>>(V16, V32, V64, V128, out, n);
}

// round 17
// speedup vs baseline: 1.0382x; 1.0382x over previous
#include <cuda_runtime.h>
#include <cuda_bf16.h>

// CompositeValueNoise, spatially-binned v15 = R14 (best, 94.0us) + PDL.
// R16's corner-reuse regressed (occupancy collapse) and is reverted.
// Programmatic Dependent Launch: scatter launches while scan drains and
// prologues its independent work (x stream loads + key ALU) before
// cudaGridDependencySynchronize(); main likewise starts early and syncs
// before touching g_sorted. Compute bodies are byte-identical to R14.

#define N_FIELDS 4
#define MAXN 2000000
#define BBITS 6
#define BDIM (1 << BBITS)            // 64
#define NBUCK (BDIM * BDIM * BDIM)   // 262144
#define SCAN_BLKS (NBUCK / 1024)     // 256

__device__ int    g_hist[NBUCK];     // zero at load; re-zeroed by main kernel
__device__ int    g_counter;
__device__ float4 g_sorted[MAXN];

__device__ __forceinline__ int cell_key(float px, float py, float pz) {
    int ci = min(max((int)(px * (float)BDIM), 0), BDIM - 1);
    int cj = min(max((int)(py * (float)BDIM), 0), BDIM - 1);
    int ck = min(max((int)(pz * (float)BDIM), 0), BDIM - 1);
    return (ci << (2 * BBITS)) | (cj << BBITS) | ck;   // k innermost
}

__global__ void hist_kernel(const float* __restrict__ x, int n) {
    int t = blockIdx.x * blockDim.x + threadIdx.x;
    int p0 = t * 4;
    if (p0 >= n) return;
    if (p0 + 4 <= n) {
        const float4* xv = reinterpret_cast<const float4*>(x) + 3 * (size_t)t;
        float4 a = __ldcs(xv + 0), b = __ldcs(xv + 1), c = __ldcs(xv + 2);
        atomicAdd(&g_hist[cell_key(a.x, a.y, a.z)], 1);
        atomicAdd(&g_hist[cell_key(a.w, b.x, b.y)], 1);
        atomicAdd(&g_hist[cell_key(b.z, b.w, c.x)], 1);
        atomicAdd(&g_hist[cell_key(c.y, c.z, c.w)], 1);
    } else {
        for (int p = p0; p < n; ++p)
            atomicAdd(&g_hist[cell_key(x[3*p], x[3*p+1], x[3*p+2])], 1);
    }
}

// Coalesced block scan of 1024 ints; block takes its global segment base via
// one early atomicAdd on g_counter, folded into the stored prefixes, so
// g_hist ends holding ABSOLUTE exclusive bucket bases. Segment order is
// run-arbitrary; each point's slot and value are unchanged -> deterministic.
__global__ void scan1_kernel() {
    __shared__ int warp_sums[8];
    __shared__ int s_base;
    int b = blockIdx.x, t = threadIdx.x;
    int lane = t & 31, wid = t >> 5;
    int base = b * 1024 + t * 4;

    int4 v = *reinterpret_cast<int4*>(&g_hist[base]);
    int tot = v.x + v.y + v.z + v.w;

    int inc = tot;
    #pragma unroll
    for (int o = 1; o < 32; o <<= 1) {
        int u = __shfl_up_sync(0xffffffffu, inc, o);
        if (lane >= o) inc += u;
    }
    if (lane == 31) warp_sums[wid] = inc;
    __syncthreads();
    if (wid == 0 && lane < 8) {
        int w = warp_sums[lane];
        #pragma unroll
        for (int o = 1; o < 8; o <<= 1) {
            int u = __shfl_up_sync(0xffu, w, o);
            if (lane >= o) w += u;
        }
        warp_sums[lane] = w;
        if (lane == 7) s_base = atomicAdd(&g_counter, w);  // w == block total
    }
    __syncthreads();
    int excl = s_base + (wid ? warp_sums[wid - 1] : 0) + inc - tot;

    int4 r;
    r.x = excl;
    r.y = excl + v.x;
    r.z = excl + v.x + v.y;
    r.w = excl + v.x + v.y + v.z;
    *reinterpret_cast<int4*>(&g_hist[base]) = r;
}

// PDL secondary: prologue (x loads + keys) runs while scan1 finishes; the
// grid-dependency sync orders it before the g_hist atomics.
__global__ void scatter_kernel(const float* __restrict__ x, int n) {
    int t = blockIdx.x * blockDim.x + threadIdx.x;
    int p0 = t * 4;

    if (p0 + 4 <= n) {
        const float4* xv = reinterpret_cast<const float4*>(x) + 3 * (size_t)t;
        float4 a = __ldcs(xv + 0), b = __ldcs(xv + 1), c = __ldcs(xv + 2);
        int k0 = cell_key(a.x, a.y, a.z);
        int k1 = cell_key(a.w, b.x, b.y);
        int k2 = cell_key(b.z, b.w, c.x);
        int k3 = cell_key(c.y, c.z, c.w);

        cudaGridDependencySynchronize();   // wait for scan1's bases

        int q0 = atomicAdd(&g_hist[k0], 1);
        __stcg(&g_sorted[q0], make_float4(a.x, a.y, a.z, __int_as_float(p0 + 0)));
        int q1 = atomicAdd(&g_hist[k1], 1);
        __stcg(&g_sorted[q1], make_float4(a.w, b.x, b.y, __int_as_float(p0 + 1)));
        int q2 = atomicAdd(&g_hist[k2], 1);
        __stcg(&g_sorted[q2], make_float4(b.z, b.w, c.x, __int_as_float(p0 + 2)));
        int q3 = atomicAdd(&g_hist[k3], 1);
        __stcg(&g_sorted[q3], make_float4(c.y, c.z, c.w, __int_as_float(p0 + 3)));
    } else {
        cudaGridDependencySynchronize();
        for (int p = p0; p < n; ++p) {
            int pos = atomicAdd(&g_hist[cell_key(x[3*p], x[3*p+1], x[3*p+2])], 1);
            __stcg(&g_sorted[pos], make_float4(x[3*p], x[3*p+1], x[3*p+2],
                                               __int_as_float(p)));
        }
    }
}

__device__ __forceinline__ float4 ld4(const float* __restrict__ p) {
    return __ldg(reinterpret_cast<const float4*>(p));
}

__device__ __forceinline__ float4 lerp4(float4 a, float4 b, float w) {
    float4 r;
    r.x = fmaf(w, b.x - a.x, a.x);
    r.y = fmaf(w, b.y - a.y, a.y);
    r.z = fmaf(w, b.z - a.z, a.z);
    r.w = fmaf(w, b.w - a.w, a.w);
    return r;
}

struct Lv {
    const float* base;
    int s0, s1;
    float wx, wy, wz;
};

__device__ __forceinline__ Lv prep(const float* __restrict__ V, int res,
                                   float px, float py, float pz) {
    const float resf = (float)res;
    float xs = px * resf, ys = py * resf, zs = pz * resf;
    // x in [0,1) and xs >= 0: trunc == floor.
    int i0 = (int)xs, j0 = (int)ys, k0 = (int)zs;
    float tx = xs - (float)i0, ty = ys - (float)j0, tz = zs - (float)k0;
    Lv L;
    L.wx = (3.0f - 2.0f * tx) * tx * tx;
    L.wy = (3.0f - 2.0f * ty) * ty * ty;
    L.wz = (3.0f - 2.0f * tz) * tz * tz;
    const int r1 = res + 1;
    L.s1 = r1 * N_FIELDS;
    L.s0 = r1 * L.s1;
    L.base = V + (size_t)i0 * L.s0 + (size_t)j0 * L.s1 + (size_t)k0 * N_FIELDS;
    return L;
}

__device__ __forceinline__ void do_loads8(const Lv& L, float4 v[8]) {
    v[0] = ld4(L.base);
    v[1] = ld4(L.base + N_FIELDS);
    v[2] = ld4(L.base + L.s1);
    v[3] = ld4(L.base + L.s1 + N_FIELDS);
    v[4] = ld4(L.base + L.s0);
    v[5] = ld4(L.base + L.s0 + N_FIELDS);
    v[6] = ld4(L.base + L.s0 + L.s1);
    v[7] = ld4(L.base + L.s0 + L.s1 + N_FIELDS);
}

__device__ __forceinline__ float4 interp8(const Lv& L, const float4 v[8]) {
    // reference order: dim0 (wx), dim1 (wy), dim2 (wz)
    float4 a00 = lerp4(v[0], v[4], L.wx);
    float4 a01 = lerp4(v[1], v[5], L.wx);
    float4 a10 = lerp4(v[2], v[6], L.wx);
    float4 a11 = lerp4(v[3], v[7], L.wx);
    float4 b0 = lerp4(a00, a10, L.wy);
    float4 b1 = lerp4(a01, a11, L.wy);
    return lerp4(b0, b1, L.wz);
}

__global__ void __launch_bounds__(128, 12) composite_value_noise_kernel(
    const float* __restrict__ V16,
    const float* __restrict__ V32,
    const float* __restrict__ V64,
    const float* __restrict__ V128,
    float* __restrict__ out,
    int n)
{
    // PDL secondary: wait for scatter before touching g_sorted / g_hist.
    cudaGridDependencySynchronize();

    int p = blockIdx.x * blockDim.x + threadIdx.x;

    if (p < n) {
        float4 pt = __ldcs(&g_sorted[p]);
        const float px = pt.x, py = pt.y, pz = pt.z;
        const int   idx = __float_as_int(pt.w);

        // Pair 1: V16 + V32 — 16 loads issued before interpolation math.
        Lv l0 = prep(V16, 16, px, py, pz);
        Lv l1 = prep(V32, 32, px, py, pz);
        float4 va[8], vb[8];
        do_loads8(l0, va);
        do_loads8(l1, vb);
        float4 n0 = interp8(l0, va);
        float4 n1 = interp8(l1, vb);

        // Pair 2: V64 + V128.
        Lv l2 = prep(V64, 64, px, py, pz);
        Lv l3 = prep(V128, 128, px, py, pz);
        do_loads8(l2, va);
        do_loads8(l3, vb);
        float4 n2 = interp8(l2, va);
        float4 n3 = interp8(l3, vb);

        float4 acc;
        acc.x = fmaf(0.125f, n3.x, fmaf(0.25f, n2.x, fmaf(0.5f, n1.x, n0.x)));
        acc.y = fmaf(0.125f, n3.y, fmaf(0.25f, n2.y, fmaf(0.5f, n1.y, n0.y)));
        acc.z = fmaf(0.125f, n3.z, fmaf(0.25f, n2.z, fmaf(0.5f, n1.z, n0.z)));
        acc.w = fmaf(0.125f, n3.w, fmaf(0.25f, n2.w, fmaf(0.5f, n1.w, n0.w)));

        __stcg(reinterpret_cast<float4*>(out) + idx, acc);
    }

    // Tail: restore the "g_hist is zero" invariant for the next invocation
    // (main kernel never reads g_hist, so this is safe within this launch).
    int z = blockIdx.x * blockDim.x + threadIdx.x;
    if (z < NBUCK / 4)
        __stcg(reinterpret_cast<int4*>(g_hist) + z, make_int4(0, 0, 0, 0));
    if (z == 0) g_counter = 0;
}

extern "C" void kernel_launch(void* const* d_in, const int* in_sizes, int n_in,
                              void* d_out, int out_size) {
    const float* x    = (const float*)d_in[0];
    const float* V16  = (const float*)d_in[1];
    const float* V32  = (const float*)d_in[2];
    const float* V64  = (const float*)d_in[3];
    const float* V128 = (const float*)d_in[4];
    float* out = (float*)d_out;

    int n = in_sizes[0] / 3;
    const int T = 256;
    int nquads = (n + 3) / 4;

    hist_kernel<<<(nquads + T - 1) / T, T>>>(x, n);
    scan1_kernel<<<SCAN_BLKS, 256>>>();

    // PDL launches: secondary may start while primary drains; the device-side
    // cudaGridDependencySynchronize() enforces ordering.
    cudaLaunchAttribute pdl[1];
    pdl[0].id = cudaLaunchAttributeProgrammaticStreamSerialization;
    pdl[0].val.programmaticStreamSerializationAllowed = 1;

    {
        cudaLaunchConfig_t cfg = {};
        cfg.gridDim = dim3((nquads + T - 1) / T);
        cfg.blockDim = dim3(T);
        cfg.attrs = pdl;
        cfg.numAttrs = 1;
        cfg.stream = 0;
        cudaLaunchKernelEx(&cfg, scatter_kernel, x, n);
    }
    {
        const int TM = 128;
        cudaLaunchConfig_t cfg = {};
        cfg.gridDim = dim3((n + TM - 1) / TM);
        cfg.blockDim = dim3(TM);
        cfg.attrs = pdl;
        cfg.numAttrs = 1;
        cfg.stream = 0;
        cudaLaunchKernelEx(&cfg, composite_value_noise_kernel,
                           V16, V32, V64, V128, out, n);
    }
}